// round 3
// baseline (speedup 1.0000x reference)
#include <cuda_runtime.h>
#include <math.h>
#include <stdint.h>

#define B 4096
#define D 256
#define NR 4
#define TEMP_INV 10.0f
#define TILE 128
#define NBLK 32          // B / TILE

// -------- scratch ----------------------------------------------------------
__device__ float g_pn[B * D];                 // tf32-rounded normalized projections
__device__ float g_sim[(size_t)B * B];        // similarity (upper-tri tiles only)
__device__ float g_pm[NBLK * B];              // per (coltile, row) LSE partial max
__device__ float g_ps[NBLK * B];              // per (coltile, row) LSE partial sum
__device__ float g_lse[B];
__device__ float g_acc[8];                    // zero-initialized; finalize re-zeros

// -------- helpers ----------------------------------------------------------
__device__ __forceinline__ float block_reduce_sum(float v, float* sh) {
    int t = threadIdx.x;
    sh[t] = v;
    __syncthreads();
    for (int s = blockDim.x >> 1; s > 0; s >>= 1) {
        if (t < s) sh[t] += sh[t + s];
        __syncthreads();
    }
    float r = sh[0];
    __syncthreads();
    return r;
}

__device__ __forceinline__ void lse_merge(float& m, float& s, float m2, float s2) {
    float M = fmaxf(m, m2);
    s = s * expf(m - M) + s2 * expf(m2 - M);   // -1e30 sentinel: exp underflows to 0
    m = M;
}

__device__ __forceinline__ void lse_push(float& m, float& s, float v) {
    if (v > m) { s = s * expf(m - v) + 1.0f; m = v; }
    else         s += expf(v - m);
}

__device__ __forceinline__ uint32_t f2tf32(float x) {
    uint32_t r;
    asm("cvt.rna.tf32.f32 %0, %1;" : "=r"(r) : "f"(x));
    return r;
}

__device__ __forceinline__ void mma_tf32(float c[4], const uint32_t a[4],
                                         uint32_t b0, uint32_t b1) {
    asm volatile(
        "mma.sync.aligned.m16n8k8.row.col.f32.tf32.tf32.f32 "
        "{%0,%1,%2,%3}, {%4,%5,%6,%7}, {%8,%9}, {%0,%1,%2,%3};\n"
        : "+f"(c[0]), "+f"(c[1]), "+f"(c[2]), "+f"(c[3])
        : "r"(a[0]), "r"(a[1]), "r"(a[2]), "r"(a[3]), "r"(b0), "r"(b1));
}

__device__ __forceinline__ void cp16(void* smem_dst, const void* gsrc) {
    uint32_t d = (uint32_t)__cvta_generic_to_shared(smem_dst);
    asm volatile("cp.async.ca.shared.global [%0], [%1], 16;\n" :: "r"(d), "l"(gsrc));
}
#define CP_COMMIT() asm volatile("cp.async.commit_group;\n" ::: "memory")
#define CP_WAIT(n)  asm volatile("cp.async.wait_group %0;\n" :: "n"(n) : "memory")

// -------- 1: prep = normalize (all blocks) + focal/region (blocks < 16) ----
__global__ __launch_bounds__(256) void prep_kernel(const float* __restrict__ proj,
                                                   const float* __restrict__ logits,
                                                   const float* __restrict__ rp,
                                                   const int* __restrict__ labels) {
    // --- normalize: one warp per row, 8 rows per block ---
    {
        int row  = blockIdx.x * 8 + (threadIdx.x >> 5);
        int lane = threadIdx.x & 31;
        const float* src = proj + (size_t)row * D;
        float v[8];
        float ss = 0.0f;
#pragma unroll
        for (int k = 0; k < 8; k++) { v[k] = src[lane + 32 * k]; ss += v[k] * v[k]; }
#pragma unroll
        for (int o = 16; o > 0; o >>= 1) ss += __shfl_xor_sync(0xFFFFFFFFu, ss, o);
        float inv = 1.0f / fmaxf(sqrtf(ss), 1e-12f);
        float* dst = g_pn + (size_t)row * D;
#pragma unroll
        for (int k = 0; k < 8; k++) dst[lane + 32 * k] = __uint_as_float(f2tf32(v[k] * inv));
    }

    // --- focal + region: 16 blocks cover all B items ---
    if (blockIdx.x < 16) {
        int b = blockIdx.x * 256 + threadIdx.x;
        int y = labels[b];
        float z0 = logits[2 * b] / 1.5f, z1 = logits[2 * b + 1] / 1.5f;
        float m  = fmaxf(z0, z1);
        float l  = m + logf(expf(z0 - m) + expf(z1 - m));
        float ce = l - (y ? z1 : z0);
        float pt = expf(-ce);
        float om = 1.0f - pt;
        float focal = om * om * ce;
        float cpd = y ? 1.0f : 0.0f, cct = y ? 0.0f : 1.0f;

        float p[NR][2], le[NR][2], ent[NR];
        float ce_sum = 0.0f;
#pragma unroll
        for (int r = 0; r < NR; r++) {
            float a0 = rp[((size_t)r * B + b) * 2];
            float a1 = rp[((size_t)r * B + b) * 2 + 1];
            float mm = fmaxf(a0, a1);
            float ll = mm + logf(expf(a0 - mm) + expf(a1 - mm));
            float lp0 = a0 - ll, lp1 = a1 - ll;
            p[r][0] = expf(lp0); p[r][1] = expf(lp1);
            le[r][0] = logf(p[r][0] + 1e-10f);
            le[r][1] = logf(p[r][1] + 1e-10f);
            ent[r] = p[r][0] * lp0 + p[r][1] * lp1;
            ce_sum += -(y ? lp1 : lp0);
        }
        float S = 0.0f;
#pragma unroll
        for (int i = 0; i < NR; i++)
#pragma unroll
            for (int j = i + 1; j < NR; j++)
                S += ent[j] - (p[j][0] * le[i][0] + p[j][1] * le[i][1]);
        float Spd = y ? S : 0.0f, Sct = y ? 0.0f : S;

        __shared__ float sh[256];
        float t;
        t = block_reduce_sum(focal, sh);  if (threadIdx.x == 0) atomicAdd(&g_acc[0], t);
        t = block_reduce_sum(cpd, sh);    if (threadIdx.x == 0) atomicAdd(&g_acc[1], t);
        t = block_reduce_sum(cct, sh);    if (threadIdx.x == 0) atomicAdd(&g_acc[2], t);
        t = block_reduce_sum(Spd, sh);    if (threadIdx.x == 0) atomicAdd(&g_acc[3], t);
        t = block_reduce_sum(Sct, sh);    if (threadIdx.x == 0) atomicAdd(&g_acc[4], t);
        t = block_reduce_sum(ce_sum, sh); if (threadIdx.x == 0) atomicAdd(&g_acc[5], t);
    }
}

// -------- 2: sim GEMM (tf32 mma, cp.async double-buffer) + LSE partials ----
// Upper-triangle tiles only. Epilogue stores the tile and emits masked-LSE
// partials for both orientations; no mirror write, no later LSE pass.
#define SROW 20   // smem row stride in floats (80 B: 16B-aligned, conflict-free)
__global__ __launch_bounds__(256) void sim_kernel(const int* __restrict__ labels) {
    int bi = blockIdx.y, bj = blockIdx.x;
    if (bi > bj) return;

    __shared__ float stile[2][2][TILE][SROW];   // [stage][A|B][row][k]
    __shared__ int   lA[TILE], lB[TILE];
    __shared__ float red_m[4][TILE], red_s[4][TILE];

    int t = threadIdx.x, lane = t & 31, warp = t >> 5;
    int wr = warp & 3, wc = warp >> 2;
    int tig = lane & 3, grp = lane >> 2;
    int rowA = bi * TILE, rowB = bj * TILE;

    if (t < TILE)            lA[t]       = labels[rowA + t];
    else                     lB[t - 128] = labels[rowB + (t - 128)];

    float c[2][8][4];
#pragma unroll
    for (int mt = 0; mt < 2; mt++)
#pragma unroll
        for (int nt = 0; nt < 8; nt++)
#pragma unroll
            for (int q = 0; q < 4; q++) c[mt][nt][q] = 0.0f;

    // stage loader: 128x16 floats per matrix = 512 float4, 256 threads x 2
#define LOAD_STAGE(st, k0)                                                      \
    {                                                                           \
        _Pragma("unroll")                                                       \
        for (int l = 0; l < 2; l++) {                                           \
            int idx = t + 256 * l;                                              \
            int r = idx >> 2, cf = (idx & 3) * 4;                               \
            cp16(&stile[st][0][r][cf], &g_pn[(size_t)(rowA + r) * D + (k0) + cf]); \
            cp16(&stile[st][1][r][cf], &g_pn[(size_t)(rowB + r) * D + (k0) + cf]); \
        }                                                                       \
    }

    LOAD_STAGE(0, 0);
    CP_COMMIT();

    for (int kt = 0; kt < D / 16; kt++) {
        int cur = kt & 1;
        if (kt + 1 < D / 16) {
            LOAD_STAGE((kt + 1) & 1, (kt + 1) * 16);
            CP_COMMIT();
            CP_WAIT(1);
        } else {
            CP_WAIT(0);
        }
        __syncthreads();
#pragma unroll
        for (int ks = 0; ks < 2; ks++) {
            int kb = ks * 8;
            uint32_t a[2][4];
#pragma unroll
            for (int mt = 0; mt < 2; mt++) {
                int r = wr * 32 + mt * 16 + grp;
                a[mt][0] = __float_as_uint(stile[cur][0][r][kb + tig]);
                a[mt][1] = __float_as_uint(stile[cur][0][r + 8][kb + tig]);
                a[mt][2] = __float_as_uint(stile[cur][0][r][kb + tig + 4]);
                a[mt][3] = __float_as_uint(stile[cur][0][r + 8][kb + tig + 4]);
            }
#pragma unroll
            for (int nt = 0; nt < 8; nt++) {
                int bn = wc * 64 + nt * 8 + grp;
                uint32_t b0 = __float_as_uint(stile[cur][1][bn][kb + tig]);
                uint32_t b1 = __float_as_uint(stile[cur][1][bn][kb + tig + 4]);
                mma_tf32(c[0][nt], a[0], b0, b1);
                mma_tf32(c[1][nt], a[1], b0, b1);
            }
        }
        __syncthreads();
    }
#undef LOAD_STAGE

    // scale + diagonal mask
#pragma unroll
    for (int mt = 0; mt < 2; mt++)
#pragma unroll
        for (int nt = 0; nt < 8; nt++)
#pragma unroll
            for (int q = 0; q < 4; q++) c[mt][nt][q] *= TEMP_INV;

    if (bi == bj) {
#pragma unroll
        for (int mt = 0; mt < 2; mt++) {
            int gi0 = wr * 32 + mt * 16 + grp;   // local row (== local col space)
#pragma unroll
            for (int nt = 0; nt < 8; nt++) {
                int gj = wc * 64 + nt * 8 + 2 * tig;
                if (gi0 == gj)         c[mt][nt][0] = -1e9f;
                if (gi0 == gj + 1)     c[mt][nt][1] = -1e9f;
                if (gi0 + 8 == gj)     c[mt][nt][2] = -1e9f;
                if (gi0 + 8 == gj + 1) c[mt][nt][3] = -1e9f;
            }
        }
    }

    // store tile (coalesced float2)
#pragma unroll
    for (int mt = 0; mt < 2; mt++) {
        int gi0 = rowA + wr * 32 + mt * 16 + grp;
#pragma unroll
        for (int nt = 0; nt < 8; nt++) {
            int gj = rowB + wc * 64 + nt * 8 + 2 * tig;
            *(float2*)&g_sim[(size_t)gi0 * B + gj]       = make_float2(c[mt][nt][0], c[mt][nt][1]);
            *(float2*)&g_sim[(size_t)(gi0 + 8) * B + gj] = make_float2(c[mt][nt][2], c[mt][nt][3]);
        }
    }

    // ---- row-direction LSE partials: rows of bi over cols of bj -> slot [bj]
#pragma unroll
    for (int mt = 0; mt < 2; mt++) {
#pragma unroll
        for (int rr = 0; rr < 2; rr++) {
            int rloc = wr * 32 + mt * 16 + rr * 8 + grp;
            int labr = lA[rloc];
            int gi   = rowA + rloc;
            float pm = -1e30f, ps = 0.0f;
#pragma unroll
            for (int nt = 0; nt < 8; nt++) {
#pragma unroll
                for (int q = 0; q < 2; q++) {
                    int cloc = wc * 64 + nt * 8 + 2 * tig + q;
                    bool excl = (lB[cloc] == labr) && (gi != rowB + cloc);
                    if (!excl) lse_push(pm, ps, c[mt][nt][rr * 2 + q]);
                }
            }
#pragma unroll
            for (int o = 1; o < 4; o <<= 1) {
                float m2 = __shfl_xor_sync(0xFFFFFFFFu, pm, o);
                float s2 = __shfl_xor_sync(0xFFFFFFFFu, ps, o);
                lse_merge(pm, ps, m2, s2);
            }
            if (tig == 0) { red_m[wc][rloc] = pm; red_s[wc][rloc] = ps; }
        }
    }
    __syncthreads();
    if (t < TILE) {
        float m = red_m[0][t], s = red_s[0][t];
        lse_merge(m, s, red_m[1][t], red_s[1][t]);
        g_pm[bj * B + rowA + t] = m;
        g_ps[bj * B + rowA + t] = s;
    }

    // ---- col-direction LSE partials (bi<bj): rows of bj over cols of bi -> slot [bi]
    if (bi < bj) {
        __syncthreads();
        float qm[16], qs[16];
#pragma unroll
        for (int nt = 0; nt < 8; nt++) {
#pragma unroll
            for (int q = 0; q < 2; q++) {
                int cloc = wc * 64 + nt * 8 + 2 * tig + q;
                int labc = lB[cloc];
                float pm = -1e30f, ps = 0.0f;
#pragma unroll
                for (int mt = 0; mt < 2; mt++)
#pragma unroll
                    for (int rr = 0; rr < 2; rr++) {
                        int rloc = wr * 32 + mt * 16 + rr * 8 + grp;
                        if (lA[rloc] != labc) lse_push(pm, ps, c[mt][nt][rr * 2 + q]);
                    }
#pragma unroll
                for (int o = 4; o < 32; o <<= 1) {
                    float m2 = __shfl_xor_sync(0xFFFFFFFFu, pm, o);
                    float s2 = __shfl_xor_sync(0xFFFFFFFFu, ps, o);
                    lse_merge(pm, ps, m2, s2);
                }
                qm[nt * 2 + q] = pm; qs[nt * 2 + q] = ps;
            }
        }
        if (grp == 0) {  // lanes 0..3, tig = lane
#pragma unroll
            for (int nt = 0; nt < 8; nt++)
#pragma unroll
                for (int q = 0; q < 2; q++) {
                    int cloc = wc * 64 + nt * 8 + 2 * tig + q;
                    red_m[wr][cloc] = qm[nt * 2 + q];
                    red_s[wr][cloc] = qs[nt * 2 + q];
                }
        }
        __syncthreads();
        if (t < TILE) {
            float m = red_m[0][t], s = red_s[0][t];
            lse_merge(m, s, red_m[1][t], red_s[1][t]);
            lse_merge(m, s, red_m[2][t], red_s[2][t]);
            lse_merge(m, s, red_m[3][t], red_s[3][t]);
            g_pm[bi * B + rowB + t] = m;
            g_ps[bi * B + rowB + t] = s;
        }
    }
}

// -------- 3: combine 32 partials per row -> lse ----------------------------
__global__ void lse_combine_kernel() {
    int i = blockIdx.x * 256 + threadIdx.x;
    float M = -1e30f, S = 0.0f;
#pragma unroll 4
    for (int k = 0; k < NBLK; k++)
        lse_merge(M, S, g_pm[k * B + i], g_ps[k * B + i]);
    g_lse[i] = M + logf(S);
}

// -------- 4: positive-pair sum over upper-triangle tiles -------------------
__global__ __launch_bounds__(256) void pair_kernel(const int* __restrict__ labels) {
    int bi = blockIdx.y, bj = blockIdx.x;
    if (bi > bj) return;
    int rowA = bi * TILE, rowB = bj * TILE;

    __shared__ float lseA[TILE], lseB[TILE];
    __shared__ int   lA[TILE], lB[TILE];
    int t = threadIdx.x;
    if (t < TILE) { lA[t] = labels[rowA + t]; lseA[t] = g_lse[rowA + t]; }
    else {
        int u = t - TILE;
        lB[u] = labels[rowB + u]; lseB[u] = g_lse[rowB + u];
    }
    __syncthreads();

    bool off = (bi < bj);
    float acc = 0.0f;
    for (int e = t; e < TILE * TILE; e += 256) {
        int r = e >> 7, cc = e & 127;
        float s = g_sim[(size_t)(rowA + r) * B + rowB + cc];
        if (lA[r] == lB[cc] && (rowA + r) != (rowB + cc)) {
            acc += log1pf(expf(lseA[r] - s));
            if (off) acc += log1pf(expf(lseB[cc] - s));
        }
    }
    __shared__ float sh[256];
    float tot = block_reduce_sum(acc, sh);
    if (t == 0) atomicAdd(&g_acc[6], tot);
}

// -------- 5: combine + re-zero accumulators for next graph replay ----------
__global__ void finalize_kernel(float* __restrict__ out) {
    float focal = g_acc[0] / (float)B;
    float pd_cnt = g_acc[1], ct_cnt = g_acc[2];
    float pd = (pd_cnt > 0.0f) ? g_acc[3] / pd_cnt : 0.0f;
    float ct = (ct_cnt > 0.0f) ? g_acc[4] / ct_cnt : 0.0f;
    float ce = g_acc[5] / (float)B;
    float reg = (pd + ct + ce) / ((float)(NR * (NR - 1)) * 0.5f + (float)NR);
    float cont = g_acc[6] / (float)B;
    out[0] = 1.0f * focal + 0.5f * cont + 0.3f * reg;
#pragma unroll
    for (int k = 0; k < 8; k++) g_acc[k] = 0.0f;
}

// -------- launch -----------------------------------------------------------
extern "C" void kernel_launch(void* const* d_in, const int* in_sizes, int n_in,
                              void* d_out, int out_size) {
    const float* logits = (const float*)d_in[0];
    const float* proj   = (const float*)d_in[1];
    const float* rp     = (const float*)d_in[2];
    const int*   labels = (const int*)d_in[3];
    float* out = (float*)d_out;
    (void)in_sizes; (void)n_in; (void)out_size;

    prep_kernel<<<B / 8, 256>>>(proj, logits, rp, labels);
    sim_kernel<<<dim3(NBLK, NBLK), 256>>>(labels);
    lse_combine_kernel<<<B / 256, 256>>>();
    pair_kernel<<<dim3(NBLK, NBLK), 256>>>(labels);
    finalize_kernel<<<1, 1>>>(out);
}

// round 4
// speedup vs baseline: 1.4309x; 1.4309x over previous
#include <cuda_runtime.h>
#include <math.h>
#include <stdint.h>

#define B 4096
#define D 256
#define NR 4
#define TEMP_INV 10.0f
#define TILE 128
#define NBLK 32          // B / TILE
#define NTRI (NBLK * (NBLK + 1) / 2)   // 528 upper-tri tiles
#define SROW 20          // smem row stride in floats (80 B)
#define LOG2E 1.4426950408889634f
#define LN2   0.6931471805599453f

// -------- scratch ----------------------------------------------------------
__device__ float g_pn[B * D];
__device__ float g_sim[(size_t)B * B];
__device__ float g_pm[NBLK * B];
__device__ float g_ps[NBLK * B];
__device__ float g_lse[B];
__device__ float g_acc[8];

// -------- helpers ----------------------------------------------------------
__device__ __forceinline__ float block_reduce_sum(float v, float* sh) {
    int t = threadIdx.x;
    sh[t] = v;
    __syncthreads();
    for (int s = blockDim.x >> 1; s > 0; s >>= 1) {
        if (t < s) sh[t] += sh[t + s];
        __syncthreads();
    }
    float r = sh[0];
    __syncthreads();
    return r;
}

__device__ __forceinline__ void lse_merge(float& m, float& s, float m2, float s2) {
    float M = fmaxf(m, m2);
    s = s * expf(m - M) + s2 * expf(m2 - M);
    m = M;
}

__device__ __forceinline__ void lse_push(float& m, float& s, float v) {
    if (v > m) { s = s * expf(m - v) + 1.0f; m = v; }
    else         s += expf(v - m);
}

__device__ __forceinline__ uint32_t f2tf32(float x) {
    uint32_t r;
    asm("cvt.rna.tf32.f32 %0, %1;" : "=r"(r) : "f"(x));
    return r;
}

__device__ __forceinline__ float ex2a(float x) {
    float y; asm("ex2.approx.f32 %0, %1;" : "=f"(y) : "f"(x)); return y;
}
__device__ __forceinline__ float lg2a(float x) {
    float y; asm("lg2.approx.f32 %0, %1;" : "=f"(y) : "f"(x)); return y;
}

__device__ __forceinline__ void mma_tf32(float c[4], const uint32_t a[4],
                                         uint32_t b0, uint32_t b1) {
    asm volatile(
        "mma.sync.aligned.m16n8k8.row.col.f32.tf32.tf32.f32 "
        "{%0,%1,%2,%3}, {%4,%5,%6,%7}, {%8,%9}, {%0,%1,%2,%3};\n"
        : "+f"(c[0]), "+f"(c[1]), "+f"(c[2]), "+f"(c[3])
        : "r"(a[0]), "r"(a[1]), "r"(a[2]), "r"(a[3]), "r"(b0), "r"(b1));
}

__device__ __forceinline__ void ldsm4(uint32_t& r0, uint32_t& r1, uint32_t& r2,
                                      uint32_t& r3, uint32_t addr) {
    asm volatile("ldmatrix.sync.aligned.m8n8.x4.shared.b16 {%0,%1,%2,%3}, [%4];\n"
                 : "=r"(r0), "=r"(r1), "=r"(r2), "=r"(r3) : "r"(addr));
}

__device__ __forceinline__ void cp16(uint32_t smem_dst, const void* gsrc) {
    asm volatile("cp.async.ca.shared.global [%0], [%1], 16;\n" :: "r"(smem_dst), "l"(gsrc));
}
#define CP_COMMIT() asm volatile("cp.async.commit_group;\n" ::: "memory")
#define CP_WAIT(n)  asm volatile("cp.async.wait_group %0;\n" :: "n"(n) : "memory")

__device__ __forceinline__ void tri_decode(int idx, int& bi, int& bj) {
    int k = idx, r = 0;
#pragma unroll 1
    while (k >= NBLK - r) { k -= NBLK - r; r++; }
    bi = r; bj = r + k;
}

// -------- 1: prep = normalize + focal/region -------------------------------
__global__ __launch_bounds__(256) void prep_kernel(const float* __restrict__ proj,
                                                   const float* __restrict__ logits,
                                                   const float* __restrict__ rp,
                                                   const int* __restrict__ labels) {
    {
        int row  = blockIdx.x * 8 + (threadIdx.x >> 5);
        int lane = threadIdx.x & 31;
        const float* src = proj + (size_t)row * D;
        float v[8];
        float ss = 0.0f;
#pragma unroll
        for (int k = 0; k < 8; k++) { v[k] = src[lane + 32 * k]; ss += v[k] * v[k]; }
#pragma unroll
        for (int o = 16; o > 0; o >>= 1) ss += __shfl_xor_sync(0xFFFFFFFFu, ss, o);
        float inv = 1.0f / fmaxf(sqrtf(ss), 1e-12f);
        float* dst = g_pn + (size_t)row * D;
#pragma unroll
        for (int k = 0; k < 8; k++) dst[lane + 32 * k] = __uint_as_float(f2tf32(v[k] * inv));
    }

    if (blockIdx.x < 16) {
        int b = blockIdx.x * 256 + threadIdx.x;
        int y = labels[b];
        float z0 = logits[2 * b] / 1.5f, z1 = logits[2 * b + 1] / 1.5f;
        float m  = fmaxf(z0, z1);
        float l  = m + logf(expf(z0 - m) + expf(z1 - m));
        float ce = l - (y ? z1 : z0);
        float pt = expf(-ce);
        float om = 1.0f - pt;
        float focal = om * om * ce;
        float cpd = y ? 1.0f : 0.0f, cct = y ? 0.0f : 1.0f;

        float p[NR][2], le[NR][2], ent[NR];
        float ce_sum = 0.0f;
#pragma unroll
        for (int r = 0; r < NR; r++) {
            float a0 = rp[((size_t)r * B + b) * 2];
            float a1 = rp[((size_t)r * B + b) * 2 + 1];
            float mm = fmaxf(a0, a1);
            float ll = mm + logf(expf(a0 - mm) + expf(a1 - mm));
            float lp0 = a0 - ll, lp1 = a1 - ll;
            p[r][0] = expf(lp0); p[r][1] = expf(lp1);
            le[r][0] = logf(p[r][0] + 1e-10f);
            le[r][1] = logf(p[r][1] + 1e-10f);
            ent[r] = p[r][0] * lp0 + p[r][1] * lp1;
            ce_sum += -(y ? lp1 : lp0);
        }
        float S = 0.0f;
#pragma unroll
        for (int i = 0; i < NR; i++)
#pragma unroll
            for (int j = i + 1; j < NR; j++)
                S += ent[j] - (p[j][0] * le[i][0] + p[j][1] * le[i][1]);
        float Spd = y ? S : 0.0f, Sct = y ? 0.0f : S;

        __shared__ float sh[256];
        float t;
        t = block_reduce_sum(focal, sh);  if (threadIdx.x == 0) atomicAdd(&g_acc[0], t);
        t = block_reduce_sum(cpd, sh);    if (threadIdx.x == 0) atomicAdd(&g_acc[1], t);
        t = block_reduce_sum(cct, sh);    if (threadIdx.x == 0) atomicAdd(&g_acc[2], t);
        t = block_reduce_sum(Spd, sh);    if (threadIdx.x == 0) atomicAdd(&g_acc[3], t);
        t = block_reduce_sum(Sct, sh);    if (threadIdx.x == 0) atomicAdd(&g_acc[4], t);
        t = block_reduce_sum(ce_sum, sh); if (threadIdx.x == 0) atomicAdd(&g_acc[5], t);
    }
}

// -------- 2: sim GEMM (tf32 mma + ldmatrix + cp.async 2-stage) + LSE -------
__global__ __launch_bounds__(256) void sim_kernel(const int* __restrict__ labels) {
    int bi, bj;
    tri_decode(blockIdx.x, bi, bj);

    __shared__ float sA[2][TILE * SROW];   // 2 x 10 KB
    __shared__ float sB[2][TILE * SROW];
    __shared__ int   lA[TILE], lB[TILE];
    __shared__ float red_m[4][TILE], red_s[4][TILE];

    int t = threadIdx.x, lane = t & 31, warp = t >> 5;
    int wr = warp & 3, wc = warp >> 2;
    int tig = lane & 3, grp = lane >> 2;
    int rowA = bi * TILE, rowB = bj * TILE;

    if (t < TILE) lA[t] = labels[rowA + t];
    else          lB[t - TILE] = labels[rowB + (t - TILE)];

    uint32_t uA = (uint32_t)__cvta_generic_to_shared(&sA[0][0]);
    uint32_t uB = (uint32_t)__cvta_generic_to_shared(&sB[0][0]);
    // ldmatrix per-lane addressing: rows 0-7 / 8-15, chunk 0 / 1 (16B each)
    int laneRow   = (lane & 7) + ((lane >> 3) & 1) * 8;
    int laneChunk = (lane >> 4) * 16;
    uint32_t aBase = uA + (uint32_t)((wr * 32 + laneRow) * (SROW * 4) + laneChunk);
    uint32_t bBase = uB + (uint32_t)((wc * 64 + laneRow) * (SROW * 4) + laneChunk);
    const uint32_t STG = TILE * SROW * 4;  // stage stride in bytes

    // cp.async loader offsets: thread t covers rows idx>>2, 16B chunk idx&3
    int ldr0 = t >> 2, ldc0 = (t & 3);
    int ldr1 = (t + 256) >> 2, ldc1 = ((t + 256) & 3);
    uint32_t dA0 = uA + (uint32_t)(ldr0 * (SROW * 4) + ldc0 * 16);
    uint32_t dA1 = uA + (uint32_t)(ldr1 * (SROW * 4) + ldc1 * 16);
    uint32_t dB0 = dA0 - uA + uB, dB1 = dA1 - uA + uB;

    float c[2][8][4];
#pragma unroll
    for (int mt = 0; mt < 2; mt++)
#pragma unroll
        for (int nt = 0; nt < 8; nt++)
#pragma unroll
            for (int q = 0; q < 4; q++) c[mt][nt][q] = 0.0f;

#define LOAD_STAGE(st, k0)                                                          \
    {                                                                               \
        cp16(dA0 + (st) * STG, &g_pn[(size_t)(rowA + ldr0) * D + (k0) + ldc0 * 4]); \
        cp16(dB0 + (st) * STG, &g_pn[(size_t)(rowB + ldr0) * D + (k0) + ldc0 * 4]); \
        cp16(dA1 + (st) * STG, &g_pn[(size_t)(rowA + ldr1) * D + (k0) + ldc1 * 4]); \
        cp16(dB1 + (st) * STG, &g_pn[(size_t)(rowB + ldr1) * D + (k0) + ldc1 * 4]); \
    }

    LOAD_STAGE(0, 0);
    CP_COMMIT();

    for (int kt = 0; kt < D / 16; kt++) {
        uint32_t cs = (kt & 1) * STG;
        if (kt + 1 < D / 16) {
            LOAD_STAGE((kt + 1) & 1, (kt + 1) * 16);
            CP_COMMIT();
            CP_WAIT(1);
        } else {
            CP_WAIT(0);
        }
        __syncthreads();
#pragma unroll
        for (int ks = 0; ks < 2; ks++) {
            uint32_t ko = cs + ks * 32;
            uint32_t a[2][4];
            ldsm4(a[0][0], a[0][1], a[0][2], a[0][3], aBase + ko);
            ldsm4(a[1][0], a[1][1], a[1][2], a[1][3], aBase + ko + 16 * SROW * 4);
#pragma unroll
            for (int ntp = 0; ntp < 4; ntp++) {
                uint32_t b0, b1, b2, b3;
                ldsm4(b0, b1, b2, b3, bBase + ko + (uint32_t)(ntp * 16 * SROW * 4));
                mma_tf32(c[0][2 * ntp],     a[0], b0, b2);
                mma_tf32(c[0][2 * ntp + 1], a[0], b1, b3);
                mma_tf32(c[1][2 * ntp],     a[1], b0, b2);
                mma_tf32(c[1][2 * ntp + 1], a[1], b1, b3);
            }
        }
        __syncthreads();
    }
#undef LOAD_STAGE

    // scale + diagonal mask
#pragma unroll
    for (int mt = 0; mt < 2; mt++)
#pragma unroll
        for (int nt = 0; nt < 8; nt++)
#pragma unroll
            for (int q = 0; q < 4; q++) c[mt][nt][q] *= TEMP_INV;

    if (bi == bj) {
#pragma unroll
        for (int mt = 0; mt < 2; mt++) {
            int gi0 = wr * 32 + mt * 16 + grp;
#pragma unroll
            for (int nt = 0; nt < 8; nt++) {
                int gj = wc * 64 + nt * 8 + 2 * tig;
                if (gi0 == gj)         c[mt][nt][0] = -1e9f;
                if (gi0 == gj + 1)     c[mt][nt][1] = -1e9f;
                if (gi0 + 8 == gj)     c[mt][nt][2] = -1e9f;
                if (gi0 + 8 == gj + 1) c[mt][nt][3] = -1e9f;
            }
        }
    }

    // store tile (coalesced float2)
#pragma unroll
    for (int mt = 0; mt < 2; mt++) {
        int gi0 = rowA + wr * 32 + mt * 16 + grp;
#pragma unroll
        for (int nt = 0; nt < 8; nt++) {
            int gj = rowB + wc * 64 + nt * 8 + 2 * tig;
            *(float2*)&g_sim[(size_t)gi0 * B + gj]       = make_float2(c[mt][nt][0], c[mt][nt][1]);
            *(float2*)&g_sim[(size_t)(gi0 + 8) * B + gj] = make_float2(c[mt][nt][2], c[mt][nt][3]);
        }
    }

    // row-direction LSE partials -> slot [bj]
#pragma unroll
    for (int mt = 0; mt < 2; mt++) {
#pragma unroll
        for (int rr = 0; rr < 2; rr++) {
            int rloc = wr * 32 + mt * 16 + rr * 8 + grp;
            int labr = lA[rloc];
            int gi   = rowA + rloc;
            float pm = -1e30f, ps = 0.0f;
#pragma unroll
            for (int nt = 0; nt < 8; nt++) {
#pragma unroll
                for (int q = 0; q < 2; q++) {
                    int cloc = wc * 64 + nt * 8 + 2 * tig + q;
                    bool excl = (lB[cloc] == labr) && (gi != rowB + cloc);
                    if (!excl) lse_push(pm, ps, c[mt][nt][rr * 2 + q]);
                }
            }
#pragma unroll
            for (int o = 1; o < 4; o <<= 1) {
                float m2 = __shfl_xor_sync(0xFFFFFFFFu, pm, o);
                float s2 = __shfl_xor_sync(0xFFFFFFFFu, ps, o);
                lse_merge(pm, ps, m2, s2);
            }
            if (tig == 0) { red_m[wc][rloc] = pm; red_s[wc][rloc] = ps; }
        }
    }
    __syncthreads();
    if (t < TILE) {
        float m = red_m[0][t], s = red_s[0][t];
        lse_merge(m, s, red_m[1][t], red_s[1][t]);
        g_pm[bj * B + rowA + t] = m;
        g_ps[bj * B + rowA + t] = s;
    }

    // col-direction LSE partials (bi<bj) -> slot [bi]
    if (bi < bj) {
        __syncthreads();
        float qm[16], qs[16];
#pragma unroll
        for (int nt = 0; nt < 8; nt++) {
#pragma unroll
            for (int q = 0; q < 2; q++) {
                int cloc = wc * 64 + nt * 8 + 2 * tig + q;
                int labc = lB[cloc];
                float pm = -1e30f, ps = 0.0f;
#pragma unroll
                for (int mt = 0; mt < 2; mt++)
#pragma unroll
                    for (int rr = 0; rr < 2; rr++) {
                        int rloc = wr * 32 + mt * 16 + rr * 8 + grp;
                        if (lA[rloc] != labc) lse_push(pm, ps, c[mt][nt][rr * 2 + q]);
                    }
#pragma unroll
                for (int o = 4; o < 32; o <<= 1) {
                    float m2 = __shfl_xor_sync(0xFFFFFFFFu, pm, o);
                    float s2 = __shfl_xor_sync(0xFFFFFFFFu, ps, o);
                    lse_merge(pm, ps, m2, s2);
                }
                qm[nt * 2 + q] = pm; qs[nt * 2 + q] = ps;
            }
        }
        if (grp == 0) {
#pragma unroll
            for (int nt = 0; nt < 8; nt++)
#pragma unroll
                for (int q = 0; q < 2; q++) {
                    int cloc = wc * 64 + nt * 8 + 2 * tig + q;
                    red_m[wr][cloc] = qm[nt * 2 + q];
                    red_s[wr][cloc] = qs[nt * 2 + q];
                }
        }
        __syncthreads();
        if (t < TILE) {
            float m = red_m[0][t], s = red_s[0][t];
            lse_merge(m, s, red_m[1][t], red_s[1][t]);
            lse_merge(m, s, red_m[2][t], red_s[2][t]);
            lse_merge(m, s, red_m[3][t], red_s[3][t]);
            g_pm[bi * B + rowB + t] = m;
            g_ps[bi * B + rowB + t] = s;
        }
    }
}

// -------- 3: combine partials -> lse ---------------------------------------
__global__ void lse_combine_kernel() {
    int i = blockIdx.x * 256 + threadIdx.x;
    float M = -1e30f, S = 0.0f;
#pragma unroll 4
    for (int k = 0; k < NBLK; k++)
        lse_merge(M, S, g_pm[k * B + i], g_ps[k * B + i]);
    g_lse[i] = M + logf(S);
}

// -------- 4: positive-pair softplus sum (product-form, 1 ex2/positive) -----
__global__ __launch_bounds__(256) void pair_kernel(const int* __restrict__ labels) {
    int bi, bj;
    tri_decode(blockIdx.x, bi, bj);
    int rowA = bi * TILE, rowB = bj * TILE;

    __shared__ float lseA[TILE], lseB[TILE];
    __shared__ int   lA[TILE], lB[TILE];
    int t = threadIdx.x;
    if (t < TILE) { lA[t] = labels[rowA + t]; lseA[t] = g_lse[rowA + t]; }
    else {
        int u = t - TILE;
        lB[u] = labels[rowB + u]; lseB[u] = g_lse[rowB + u];
    }
    __syncthreads();

    bool off = (bi < bj);
    float acc = 0.0f, prod = 1.0f;

#pragma unroll 4
    for (int k = 0; k < 32; k++) {
        int e2 = t + (k << 8);           // float2 index in 128x128 tile
        int r  = e2 >> 6;
        int cc = (e2 & 63) * 2;
        float2 sv = *(const float2*)&g_sim[(size_t)(rowA + r) * B + rowB + cc];
#pragma unroll
        for (int q = 0; q < 2; q++) {
            int cq = cc + q;
            float s = q ? sv.y : sv.x;
            if (lA[r] == lB[cq] && (rowA + r) != (rowB + cq)) {
                float x1 = lseA[r] - s;
                acc += fmaxf(x1, 0.0f);
                prod *= (1.0f + ex2a(-fabsf(x1) * LOG2E));
                if (off) {
                    float x2 = lseB[cq] - s;
                    acc += fmaxf(x2, 0.0f);
                    prod *= (1.0f + ex2a(-fabsf(x2) * LOG2E));
                }
            }
        }
        if ((k & 7) == 7) { acc += lg2a(prod) * LN2; prod = 1.0f; }
    }

    __shared__ float sh[256];
    float tot = block_reduce_sum(acc, sh);
    if (t == 0) atomicAdd(&g_acc[6], tot);
}

// -------- 5: combine + re-zero ---------------------------------------------
__global__ void finalize_kernel(float* __restrict__ out) {
    float focal = g_acc[0] / (float)B;
    float pd_cnt = g_acc[1], ct_cnt = g_acc[2];
    float pd = (pd_cnt > 0.0f) ? g_acc[3] / pd_cnt : 0.0f;
    float ct = (ct_cnt > 0.0f) ? g_acc[4] / ct_cnt : 0.0f;
    float ce = g_acc[5] / (float)B;
    float reg = (pd + ct + ce) / ((float)(NR * (NR - 1)) * 0.5f + (float)NR);
    float cont = g_acc[6] / (float)B;
    out[0] = 1.0f * focal + 0.5f * cont + 0.3f * reg;
#pragma unroll
    for (int k = 0; k < 8; k++) g_acc[k] = 0.0f;
}

// -------- launch -----------------------------------------------------------
extern "C" void kernel_launch(void* const* d_in, const int* in_sizes, int n_in,
                              void* d_out, int out_size) {
    const float* logits = (const float*)d_in[0];
    const float* proj   = (const float*)d_in[1];
    const float* rp     = (const float*)d_in[2];
    const int*   labels = (const int*)d_in[3];
    float* out = (float*)d_out;
    (void)in_sizes; (void)n_in; (void)out_size;

    prep_kernel<<<B / 8, 256>>>(proj, logits, rp, labels);
    sim_kernel<<<NTRI, 256>>>(labels);
    lse_combine_kernel<<<B / 256, 256>>>();
    pair_kernel<<<NTRI, 256>>>(labels);
    finalize_kernel<<<1, 1>>>(out);
}

// round 5
// speedup vs baseline: 2.3828x; 1.6653x over previous
#include <cuda_runtime.h>
#include <math.h>
#include <stdint.h>

#define B 4096
#define D 256
#define NR 4
#define TEMP_INV 10.0f
#define TILE 128
#define NBLK 32                          // B / TILE
#define NTRI (NBLK * (NBLK + 1) / 2)     // 528 upper-tri tiles
#define SROW 20                          // smem row stride in floats (80 B)
#define LOG2E 1.4426950408889634f
#define LN2   0.6931471805599453f
#define MFIX  10.0f                      // fixed LSE max: sim in [-10,10]

// -------- scratch ----------------------------------------------------------
__device__ float g_pn[B * D];
__device__ float g_sim[(size_t)B * B];
__device__ float g_ps[NBLK * B];         // per (tile-slot, row) sum of masked exp(v-10)
__device__ float g_acc[8];

// -------- helpers ----------------------------------------------------------
__device__ __forceinline__ float block_reduce_sum(float v, float* sh) {
    int t = threadIdx.x;
    sh[t] = v;
    __syncthreads();
    for (int s = blockDim.x >> 1; s > 0; s >>= 1) {
        if (t < s) sh[t] += sh[t + s];
        __syncthreads();
    }
    float r = sh[0];
    __syncthreads();
    return r;
}

__device__ __forceinline__ uint32_t f2tf32(float x) {
    uint32_t r;
    asm("cvt.rna.tf32.f32 %0, %1;" : "=r"(r) : "f"(x));
    return r;
}

__device__ __forceinline__ float ex2a(float x) {
    float y; asm("ex2.approx.f32 %0, %1;" : "=f"(y) : "f"(x)); return y;
}
__device__ __forceinline__ float lg2a(float x) {
    float y; asm("lg2.approx.f32 %0, %1;" : "=f"(y) : "f"(x)); return y;
}

__device__ __forceinline__ void mma_tf32(float c[4], const uint32_t a[4],
                                         uint32_t b0, uint32_t b1) {
    asm volatile(
        "mma.sync.aligned.m16n8k8.row.col.f32.tf32.tf32.f32 "
        "{%0,%1,%2,%3}, {%4,%5,%6,%7}, {%8,%9}, {%0,%1,%2,%3};\n"
        : "+f"(c[0]), "+f"(c[1]), "+f"(c[2]), "+f"(c[3])
        : "r"(a[0]), "r"(a[1]), "r"(a[2]), "r"(a[3]), "r"(b0), "r"(b1));
}

__device__ __forceinline__ void ldsm4(uint32_t& r0, uint32_t& r1, uint32_t& r2,
                                      uint32_t& r3, uint32_t addr) {
    asm volatile("ldmatrix.sync.aligned.m8n8.x4.shared.b16 {%0,%1,%2,%3}, [%4];\n"
                 : "=r"(r0), "=r"(r1), "=r"(r2), "=r"(r3) : "r"(addr));
}

__device__ __forceinline__ void cp16(uint32_t smem_dst, const void* gsrc) {
    asm volatile("cp.async.ca.shared.global [%0], [%1], 16;\n" :: "r"(smem_dst), "l"(gsrc));
}
#define CP_COMMIT() asm volatile("cp.async.commit_group;\n" ::: "memory")
#define CP_WAIT(n)  asm volatile("cp.async.wait_group %0;\n" :: "n"(n) : "memory")

__device__ __forceinline__ void tri_decode(int idx, int& bi, int& bj) {
    int k = idx, r = 0;
#pragma unroll 1
    while (k >= NBLK - r) { k -= NBLK - r; r++; }
    bi = r; bj = r + k;
}

// -------- 1: prep = normalize + focal/region -------------------------------
__global__ __launch_bounds__(256) void prep_kernel(const float* __restrict__ proj,
                                                   const float* __restrict__ logits,
                                                   const float* __restrict__ rp,
                                                   const int* __restrict__ labels) {
    {
        int row  = blockIdx.x * 8 + (threadIdx.x >> 5);
        int lane = threadIdx.x & 31;
        const float* src = proj + (size_t)row * D;
        float v[8];
        float ss = 0.0f;
#pragma unroll
        for (int k = 0; k < 8; k++) { v[k] = src[lane + 32 * k]; ss += v[k] * v[k]; }
#pragma unroll
        for (int o = 16; o > 0; o >>= 1) ss += __shfl_xor_sync(0xFFFFFFFFu, ss, o);
        float inv = 1.0f / fmaxf(sqrtf(ss), 1e-12f);
        float* dst = g_pn + (size_t)row * D;
#pragma unroll
        for (int k = 0; k < 8; k++) dst[lane + 32 * k] = __uint_as_float(f2tf32(v[k] * inv));
    }

    if (blockIdx.x < 16) {
        int b = blockIdx.x * 256 + threadIdx.x;
        int y = labels[b];
        float z0 = logits[2 * b] / 1.5f, z1 = logits[2 * b + 1] / 1.5f;
        float m  = fmaxf(z0, z1);
        float l  = m + logf(expf(z0 - m) + expf(z1 - m));
        float ce = l - (y ? z1 : z0);
        float pt = expf(-ce);
        float om = 1.0f - pt;
        float focal = om * om * ce;
        float cpd = y ? 1.0f : 0.0f, cct = y ? 0.0f : 1.0f;

        float p[NR][2], le[NR][2], ent[NR];
        float ce_sum = 0.0f;
#pragma unroll
        for (int r = 0; r < NR; r++) {
            float a0 = rp[((size_t)r * B + b) * 2];
            float a1 = rp[((size_t)r * B + b) * 2 + 1];
            float mm = fmaxf(a0, a1);
            float ll = mm + logf(expf(a0 - mm) + expf(a1 - mm));
            float lp0 = a0 - ll, lp1 = a1 - ll;
            p[r][0] = expf(lp0); p[r][1] = expf(lp1);
            le[r][0] = logf(p[r][0] + 1e-10f);
            le[r][1] = logf(p[r][1] + 1e-10f);
            ent[r] = p[r][0] * lp0 + p[r][1] * lp1;
            ce_sum += -(y ? lp1 : lp0);
        }
        float S = 0.0f;
#pragma unroll
        for (int i = 0; i < NR; i++)
#pragma unroll
            for (int j = i + 1; j < NR; j++)
                S += ent[j] - (p[j][0] * le[i][0] + p[j][1] * le[i][1]);
        float Spd = y ? S : 0.0f, Sct = y ? 0.0f : S;

        __shared__ float sh[256];
        float t;
        t = block_reduce_sum(focal, sh);  if (threadIdx.x == 0) atomicAdd(&g_acc[0], t);
        t = block_reduce_sum(cpd, sh);    if (threadIdx.x == 0) atomicAdd(&g_acc[1], t);
        t = block_reduce_sum(cct, sh);    if (threadIdx.x == 0) atomicAdd(&g_acc[2], t);
        t = block_reduce_sum(Spd, sh);    if (threadIdx.x == 0) atomicAdd(&g_acc[3], t);
        t = block_reduce_sum(Sct, sh);    if (threadIdx.x == 0) atomicAdd(&g_acc[4], t);
        t = block_reduce_sum(ce_sum, sh); if (threadIdx.x == 0) atomicAdd(&g_acc[5], t);
    }
}

// -------- 2: sim GEMM (tf32 mma + ldmatrix + cp.async) + masked-exp sums ---
__global__ __launch_bounds__(256) void sim_kernel(const int* __restrict__ labels) {
    int bi, bj;
    tri_decode(blockIdx.x, bi, bj);

    __shared__ float sA[2][TILE * SROW];
    __shared__ float sB[2][TILE * SROW];
    __shared__ int   lA[TILE], lB[TILE];
    __shared__ float red_s[4][TILE];

    int t = threadIdx.x, lane = t & 31, warp = t >> 5;
    int wr = warp & 3, wc = warp >> 2;
    int tig = lane & 3, grp = lane >> 2;
    int rowA = bi * TILE, rowB = bj * TILE;

    if (t < TILE) lA[t] = labels[rowA + t];
    else          lB[t - TILE] = labels[rowB + (t - TILE)];

    uint32_t uA = (uint32_t)__cvta_generic_to_shared(&sA[0][0]);
    uint32_t uB = (uint32_t)__cvta_generic_to_shared(&sB[0][0]);
    int laneRow   = (lane & 7) + ((lane >> 3) & 1) * 8;
    int laneChunk = (lane >> 4) * 16;
    uint32_t aBase = uA + (uint32_t)((wr * 32 + laneRow) * (SROW * 4) + laneChunk);
    uint32_t bBase = uB + (uint32_t)((wc * 64 + laneRow) * (SROW * 4) + laneChunk);
    const uint32_t STG = TILE * SROW * 4;

    int ldr0 = t >> 2, ldc0 = (t & 3);
    int ldr1 = (t + 256) >> 2, ldc1 = ((t + 256) & 3);
    uint32_t dA0 = uA + (uint32_t)(ldr0 * (SROW * 4) + ldc0 * 16);
    uint32_t dA1 = uA + (uint32_t)(ldr1 * (SROW * 4) + ldc1 * 16);
    uint32_t dB0 = dA0 - uA + uB, dB1 = dA1 - uA + uB;

    float c[2][8][4];
#pragma unroll
    for (int mt = 0; mt < 2; mt++)
#pragma unroll
        for (int nt = 0; nt < 8; nt++)
#pragma unroll
            for (int q = 0; q < 4; q++) c[mt][nt][q] = 0.0f;

#define LOAD_STAGE(st, k0)                                                          \
    {                                                                               \
        cp16(dA0 + (st) * STG, &g_pn[(size_t)(rowA + ldr0) * D + (k0) + ldc0 * 4]); \
        cp16(dB0 + (st) * STG, &g_pn[(size_t)(rowB + ldr0) * D + (k0) + ldc0 * 4]); \
        cp16(dA1 + (st) * STG, &g_pn[(size_t)(rowA + ldr1) * D + (k0) + ldc1 * 4]); \
        cp16(dB1 + (st) * STG, &g_pn[(size_t)(rowB + ldr1) * D + (k0) + ldc1 * 4]); \
    }

    LOAD_STAGE(0, 0);
    CP_COMMIT();

    for (int kt = 0; kt < D / 16; kt++) {
        uint32_t cs = (kt & 1) * STG;
        if (kt + 1 < D / 16) {
            LOAD_STAGE((kt + 1) & 1, (kt + 1) * 16);
            CP_COMMIT();
            CP_WAIT(1);
        } else {
            CP_WAIT(0);
        }
        __syncthreads();
#pragma unroll
        for (int ks = 0; ks < 2; ks++) {
            uint32_t ko = cs + ks * 32;
            uint32_t a[2][4];
            ldsm4(a[0][0], a[0][1], a[0][2], a[0][3], aBase + ko);
            ldsm4(a[1][0], a[1][1], a[1][2], a[1][3], aBase + ko + 16 * SROW * 4);
#pragma unroll
            for (int ntp = 0; ntp < 4; ntp++) {
                uint32_t b0, b1, b2, b3;
                ldsm4(b0, b1, b2, b3, bBase + ko + (uint32_t)(ntp * 16 * SROW * 4));
                mma_tf32(c[0][2 * ntp],     a[0], b0, b2);
                mma_tf32(c[0][2 * ntp + 1], a[0], b1, b3);
                mma_tf32(c[1][2 * ntp],     a[1], b0, b2);
                mma_tf32(c[1][2 * ntp + 1], a[1], b1, b3);
            }
        }
        __syncthreads();
    }
#undef LOAD_STAGE

    // scale + diagonal mask
#pragma unroll
    for (int mt = 0; mt < 2; mt++)
#pragma unroll
        for (int nt = 0; nt < 8; nt++)
#pragma unroll
            for (int q = 0; q < 4; q++) c[mt][nt][q] *= TEMP_INV;

    if (bi == bj) {
#pragma unroll
        for (int mt = 0; mt < 2; mt++) {
            int gi0 = wr * 32 + mt * 16 + grp;
#pragma unroll
            for (int nt = 0; nt < 8; nt++) {
                int gj = wc * 64 + nt * 8 + 2 * tig;
                if (gi0 == gj)         c[mt][nt][0] = -1e9f;
                if (gi0 == gj + 1)     c[mt][nt][1] = -1e9f;
                if (gi0 + 8 == gj)     c[mt][nt][2] = -1e9f;
                if (gi0 + 8 == gj + 1) c[mt][nt][3] = -1e9f;
            }
        }
    }

    // store tile (coalesced float2)
#pragma unroll
    for (int mt = 0; mt < 2; mt++) {
        int gi0 = rowA + wr * 32 + mt * 16 + grp;
#pragma unroll
        for (int nt = 0; nt < 8; nt++) {
            int gj = rowB + wc * 64 + nt * 8 + 2 * tig;
            *(float2*)&g_sim[(size_t)gi0 * B + gj]       = make_float2(c[mt][nt][0], c[mt][nt][1]);
            *(float2*)&g_sim[(size_t)(gi0 + 8) * B + gj] = make_float2(c[mt][nt][2], c[mt][nt][3]);
        }
    }

    // ---- masked-exp partial sums, both directions, one ex2 per element ----
    // e = (label differs) ? exp(v - 10) : 0   (diag v=-1e9 -> e=0 regardless)
    float colacc[16];
#pragma unroll
    for (int k = 0; k < 16; k++) colacc[k] = 0.0f;

#pragma unroll
    for (int mt = 0; mt < 2; mt++) {
#pragma unroll
        for (int rr = 0; rr < 2; rr++) {
            int rloc = wr * 32 + mt * 16 + rr * 8 + grp;
            int labr = lA[rloc];
            float ra = 0.0f;
#pragma unroll
            for (int nt = 0; nt < 8; nt++) {
#pragma unroll
                for (int q = 0; q < 2; q++) {
                    int cloc = wc * 64 + nt * 8 + 2 * tig + q;
                    float v = c[mt][nt][rr * 2 + q];
                    float e = ex2a((v - MFIX) * LOG2E);
                    e = (lB[cloc] != labr) ? e : 0.0f;
                    ra += e;
                    colacc[nt * 2 + q] += e;
                }
            }
            ra += __shfl_xor_sync(0xFFFFFFFFu, ra, 1);
            ra += __shfl_xor_sync(0xFFFFFFFFu, ra, 2);
            if (tig == 0) red_s[wc][rloc] = ra;
        }
    }
    __syncthreads();
    if (t < TILE) g_ps[bj * B + rowA + t] = red_s[0][t] + red_s[1][t];

    if (bi < bj) {
        __syncthreads();
#pragma unroll
        for (int k = 0; k < 16; k++) {
            colacc[k] += __shfl_xor_sync(0xFFFFFFFFu, colacc[k], 4);
            colacc[k] += __shfl_xor_sync(0xFFFFFFFFu, colacc[k], 8);
            colacc[k] += __shfl_xor_sync(0xFFFFFFFFu, colacc[k], 16);
        }
        if (grp == 0) {
#pragma unroll
            for (int nt = 0; nt < 8; nt++)
#pragma unroll
                for (int q = 0; q < 2; q++) {
                    int cloc = wc * 64 + nt * 8 + 2 * tig + q;
                    red_s[wr][cloc] = colacc[nt * 2 + q];
                }
        }
        __syncthreads();
        if (t < TILE)
            g_ps[bi * B + rowB + t] =
                red_s[0][t] + red_s[1][t] + red_s[2][t] + red_s[3][t];
    }
}

// -------- 3: pair sum (lse computed in prologue; branch-lean body) ---------
__global__ __launch_bounds__(256) void pair_kernel(const int* __restrict__ labels) {
    int bi, bj;
    tri_decode(blockIdx.x, bi, bj);
    int rowA = bi * TILE, rowB = bj * TILE;

    __shared__ float lseA[TILE], lseB[TILE];
    __shared__ int   lA[TILE], lB[TILE];
    int t = threadIdx.x;

    // prologue: lse_i = 10 + log( sum_k g_ps[k][i] ), coalesced across threads
    {
        int half = t >> 7;              // 0 -> rowA rows, 1 -> rowB rows
        int u = t & 127;
        int gi = (half ? rowB : rowA) + u;
        float S = 0.0f;
#pragma unroll
        for (int k = 0; k < NBLK; k++) S += g_ps[k * B + gi];
        float lse = MFIX + logf(S);
        if (half) { lseB[u] = lse; lB[u] = labels[gi]; }
        else      { lseA[u] = lse; lA[u] = labels[gi]; }
    }
    __syncthreads();

    int r = t >> 1;
    int cbase = (t & 1) * 64;
    int la = lA[r];
    float lsa = lseA[r];
    int dcol = (bi == bj) ? r : -1;     // excluded diagonal column
    bool off = (bi < bj);

    const float4* rowp = (const float4*)&g_sim[(size_t)(rowA + r) * B + rowB + cbase];
    float acc = 0.0f, prod = 1.0f;

#pragma unroll 4
    for (int k = 0; k < 16; k++) {
        float4 s4 = rowp[k];
        int c0 = cbase + 4 * k;
        int4   lb4  = *(const int4*)&lB[c0];
        float4 lsb4 = *(const float4*)&lseB[c0];
        float sv[4]  = {s4.x, s4.y, s4.z, s4.w};
        int   lbv[4] = {lb4.x, lb4.y, lb4.z, lb4.w};
        float lsb[4] = {lsb4.x, lsb4.y, lsb4.z, lsb4.w};
#pragma unroll
        for (int q = 0; q < 4; q++) {
            bool m = (la == lbv[q]) && (c0 + q != dcol);
            if (m) {
                float s = sv[q];
                float x1 = lsa - s;
                acc += fmaxf(x1, 0.0f);
                float e1 = ex2a(-LOG2E * fabsf(x1));
                prod = fmaf(prod, e1, prod);
                if (off) {
                    float x2 = lsb[q] - s;
                    acc += fmaxf(x2, 0.0f);
                    float e2 = ex2a(-LOG2E * fabsf(x2));
                    prod = fmaf(prod, e2, prod);
                }
            }
        }
        if ((k & 3) == 3) { acc += lg2a(prod) * LN2; prod = 1.0f; }
    }

    __shared__ float sh[256];
    float tot = block_reduce_sum(acc, sh);
    if (t == 0) atomicAdd(&g_acc[6], tot);
}

// -------- 4: combine + re-zero ---------------------------------------------
__global__ void finalize_kernel(float* __restrict__ out) {
    float focal = g_acc[0] / (float)B;
    float pd_cnt = g_acc[1], ct_cnt = g_acc[2];
    float pd = (pd_cnt > 0.0f) ? g_acc[3] / pd_cnt : 0.0f;
    float ct = (ct_cnt > 0.0f) ? g_acc[4] / ct_cnt : 0.0f;
    float ce = g_acc[5] / (float)B;
    float reg = (pd + ct + ce) / ((float)(NR * (NR - 1)) * 0.5f + (float)NR);
    float cont = g_acc[6] / (float)B;
    out[0] = 1.0f * focal + 0.5f * cont + 0.3f * reg;
#pragma unroll
    for (int k = 0; k < 8; k++) g_acc[k] = 0.0f;
}

// -------- launch -----------------------------------------------------------
extern "C" void kernel_launch(void* const* d_in, const int* in_sizes, int n_in,
                              void* d_out, int out_size) {
    const float* logits = (const float*)d_in[0];
    const float* proj   = (const float*)d_in[1];
    const float* rp     = (const float*)d_in[2];
    const int*   labels = (const int*)d_in[3];
    float* out = (float*)d_out;
    (void)in_sizes; (void)n_in; (void)out_size;

    prep_kernel<<<B / 8, 256>>>(proj, logits, rp, labels);
    sim_kernel<<<NTRI, 256>>>(labels);
    pair_kernel<<<NTRI, 256>>>(labels);
    finalize_kernel<<<1, 1>>>(out);
}

// round 6
// speedup vs baseline: 3.1198x; 1.3093x over previous
#include <cuda_runtime.h>
#include <cuda_fp16.h>
#include <cuda_bf16.h>
#include <math.h>
#include <stdint.h>

#define B 4096
#define D 256
#define NR 4
#define TEMP_INV 10.0f
#define TILE 128
#define NBLK 32                          // B / TILE
#define NTRI (NBLK * (NBLK + 1) / 2)     // 528 upper-tri tiles
#define SROW 20                          // smem row stride in floats (80 B)
#define LOG2E 1.4426950408889634f
#define LN2   0.6931471805599453f
#define MFIX  10.0f                      // fixed LSE max: sim in [-10,10]

// -------- scratch ----------------------------------------------------------
__device__ __nv_bfloat16 g_pn[B * D];    // bf16 normalized projections (2 MB)
__device__ __half g_sim[(size_t)B * B];  // similarity, fp16 (32 MB; upper tiles)
__device__ float g_ps[NBLK * B];         // per (tile-slot, row) masked exp-sums
__device__ float g_acc[8];
__device__ unsigned g_done;

// -------- helpers ----------------------------------------------------------
__device__ __forceinline__ float block_reduce_sum(float v, float* sh) {
    int t = threadIdx.x;
    sh[t] = v;
    __syncthreads();
    for (int s = blockDim.x >> 1; s > 0; s >>= 1) {
        if (t < s) sh[t] += sh[t + s];
        __syncthreads();
    }
    float r = sh[0];
    __syncthreads();
    return r;
}

__device__ __forceinline__ float ex2a(float x) {
    float y; asm("ex2.approx.f32 %0, %1;" : "=f"(y) : "f"(x)); return y;
}
__device__ __forceinline__ float lg2a(float x) {
    float y; asm("lg2.approx.f32 %0, %1;" : "=f"(y) : "f"(x)); return y;
}

__device__ __forceinline__ void mma_bf16(float c[4], const uint32_t a[4],
                                         uint32_t b0, uint32_t b1) {
    asm volatile(
        "mma.sync.aligned.m16n8k16.row.col.f32.bf16.bf16.f32 "
        "{%0,%1,%2,%3}, {%4,%5,%6,%7}, {%8,%9}, {%0,%1,%2,%3};\n"
        : "+f"(c[0]), "+f"(c[1]), "+f"(c[2]), "+f"(c[3])
        : "r"(a[0]), "r"(a[1]), "r"(a[2]), "r"(a[3]), "r"(b0), "r"(b1));
}

__device__ __forceinline__ void ldsm4(uint32_t& r0, uint32_t& r1, uint32_t& r2,
                                      uint32_t& r3, uint32_t addr) {
    asm volatile("ldmatrix.sync.aligned.m8n8.x4.shared.b16 {%0,%1,%2,%3}, [%4];\n"
                 : "=r"(r0), "=r"(r1), "=r"(r2), "=r"(r3) : "r"(addr));
}

__device__ __forceinline__ void cp16(uint32_t smem_dst, const void* gsrc) {
    asm volatile("cp.async.ca.shared.global [%0], [%1], 16;\n" :: "r"(smem_dst), "l"(gsrc));
}
#define CP_COMMIT() asm volatile("cp.async.commit_group;\n" ::: "memory")
#define CP_WAIT(n)  asm volatile("cp.async.wait_group %0;\n" :: "n"(n) : "memory")

__device__ __forceinline__ void tri_decode(int idx, int& bi, int& bj) {
    int k = idx, r = 0;
#pragma unroll 1
    while (k >= NBLK - r) { k -= NBLK - r; r++; }
    bi = r; bj = r + k;
}

// -------- 1: prep = normalize (bf16 out) + focal/region --------------------
__global__ __launch_bounds__(256) void prep_kernel(const float* __restrict__ proj,
                                                   const float* __restrict__ logits,
                                                   const float* __restrict__ rp,
                                                   const int* __restrict__ labels) {
    {
        int row  = blockIdx.x * 8 + (threadIdx.x >> 5);
        int lane = threadIdx.x & 31;
        const float* src = proj + (size_t)row * D;
        float v[8];
        float ss = 0.0f;
#pragma unroll
        for (int k = 0; k < 8; k++) { v[k] = src[lane + 32 * k]; ss += v[k] * v[k]; }
#pragma unroll
        for (int o = 16; o > 0; o >>= 1) ss += __shfl_xor_sync(0xFFFFFFFFu, ss, o);
        float inv = 1.0f / fmaxf(sqrtf(ss), 1e-12f);
        __nv_bfloat16* dst = g_pn + (size_t)row * D;
#pragma unroll
        for (int k = 0; k < 8; k++) dst[lane + 32 * k] = __float2bfloat16(v[k] * inv);
    }

    if (blockIdx.x < 16) {
        int b = blockIdx.x * 256 + threadIdx.x;
        int y = labels[b];
        float z0 = logits[2 * b] / 1.5f, z1 = logits[2 * b + 1] / 1.5f;
        float m  = fmaxf(z0, z1);
        float l  = m + logf(expf(z0 - m) + expf(z1 - m));
        float ce = l - (y ? z1 : z0);
        float pt = expf(-ce);
        float om = 1.0f - pt;
        float focal = om * om * ce;
        float cpd = y ? 1.0f : 0.0f, cct = y ? 0.0f : 1.0f;

        float p[NR][2], le[NR][2], ent[NR];
        float ce_sum = 0.0f;
#pragma unroll
        for (int r = 0; r < NR; r++) {
            float a0 = rp[((size_t)r * B + b) * 2];
            float a1 = rp[((size_t)r * B + b) * 2 + 1];
            float mm = fmaxf(a0, a1);
            float ll = mm + logf(expf(a0 - mm) + expf(a1 - mm));
            float lp0 = a0 - ll, lp1 = a1 - ll;
            p[r][0] = expf(lp0); p[r][1] = expf(lp1);
            le[r][0] = logf(p[r][0] + 1e-10f);
            le[r][1] = logf(p[r][1] + 1e-10f);
            ent[r] = p[r][0] * lp0 + p[r][1] * lp1;
            ce_sum += -(y ? lp1 : lp0);
        }
        float S = 0.0f;
#pragma unroll
        for (int i = 0; i < NR; i++)
#pragma unroll
            for (int j = i + 1; j < NR; j++)
                S += ent[j] - (p[j][0] * le[i][0] + p[j][1] * le[i][1]);
        float Spd = y ? S : 0.0f, Sct = y ? 0.0f : S;

        __shared__ float sh[256];
        float t;
        t = block_reduce_sum(focal, sh);  if (threadIdx.x == 0) atomicAdd(&g_acc[0], t);
        t = block_reduce_sum(cpd, sh);    if (threadIdx.x == 0) atomicAdd(&g_acc[1], t);
        t = block_reduce_sum(cct, sh);    if (threadIdx.x == 0) atomicAdd(&g_acc[2], t);
        t = block_reduce_sum(Spd, sh);    if (threadIdx.x == 0) atomicAdd(&g_acc[3], t);
        t = block_reduce_sum(Sct, sh);    if (threadIdx.x == 0) atomicAdd(&g_acc[4], t);
        t = block_reduce_sum(ce_sum, sh); if (threadIdx.x == 0) atomicAdd(&g_acc[5], t);
    }
}

// -------- 2: sim GEMM (bf16 m16n8k16 mma + ldmatrix + cp.async) + exp sums -
// smem row: 32 bf16 (64 B data) per stage, stride 80 B (conflict-free).
__global__ __launch_bounds__(256) void sim_kernel(const int* __restrict__ labels) {
    int bi, bj;
    tri_decode(blockIdx.x, bi, bj);

    __shared__ float sA[2][TILE * SROW];   // bytes reused for bf16 rows
    __shared__ float sB[2][TILE * SROW];
    __shared__ int   lA[TILE], lB[TILE];
    __shared__ float red_s[4][TILE];

    int t = threadIdx.x, lane = t & 31, warp = t >> 5;
    int wr = warp & 3, wc = warp >> 2;
    int tig = lane & 3, grp = lane >> 2;
    int rowA = bi * TILE, rowB = bj * TILE;

    if (t < TILE) lA[t] = labels[rowA + t];
    else          lB[t - TILE] = labels[rowB + (t - TILE)];

    uint32_t uA = (uint32_t)__cvta_generic_to_shared(&sA[0][0]);
    uint32_t uB = (uint32_t)__cvta_generic_to_shared(&sB[0][0]);
    // ldmatrix x4 canonical addressing: 16 rows, 2 k-chunks of 16 B
    int laneRow   = lane & 15;
    int laneChunk = (lane >> 4) * 16;
    uint32_t aBase = uA + (uint32_t)((wr * 32 + laneRow) * 80 + laneChunk);
    uint32_t bBase = uB + (uint32_t)((wc * 64 + laneRow) * 80 + laneChunk);
    const uint32_t STG = TILE * 80;

    // loader: per matrix 128 rows x 4 16B-chunks = 512 cp; 2 per thread
    int ldr0 = t >> 2, ldc0 = t & 3;        // rows 0-63
    uint32_t dA0 = uA + (uint32_t)(ldr0 * 80 + ldc0 * 16);
    uint32_t dA1 = dA0 + 64 * 80;           // rows 64-127
    uint32_t dB0 = dA0 - uA + uB, dB1 = dA1 - uA + uB;

    float c[2][8][4];
#pragma unroll
    for (int mt = 0; mt < 2; mt++)
#pragma unroll
        for (int nt = 0; nt < 8; nt++)
#pragma unroll
            for (int q = 0; q < 4; q++) c[mt][nt][q] = 0.0f;

#define LOAD_STAGE(st, k0)                                                               \
    {                                                                                    \
        cp16(dA0 + (st) * STG, &g_pn[(size_t)(rowA + ldr0) * D + (k0) + ldc0 * 8]);      \
        cp16(dB0 + (st) * STG, &g_pn[(size_t)(rowB + ldr0) * D + (k0) + ldc0 * 8]);      \
        cp16(dA1 + (st) * STG, &g_pn[(size_t)(rowA + 64 + ldr0) * D + (k0) + ldc0 * 8]); \
        cp16(dB1 + (st) * STG, &g_pn[(size_t)(rowB + 64 + ldr0) * D + (k0) + ldc0 * 8]); \
    }

    LOAD_STAGE(0, 0);
    CP_COMMIT();

    for (int kt = 0; kt < D / 32; kt++) {       // 8 stages of K=32 bf16
        uint32_t cs = (kt & 1) * STG;
        if (kt + 1 < D / 32) {
            LOAD_STAGE((kt + 1) & 1, (kt + 1) * 32);
            CP_COMMIT();
            CP_WAIT(1);
        } else {
            CP_WAIT(0);
        }
        __syncthreads();
#pragma unroll
        for (int ks = 0; ks < 2; ks++) {        // two k16 halves
            uint32_t ko = cs + ks * 32;
            uint32_t a[2][4];
            ldsm4(a[0][0], a[0][1], a[0][2], a[0][3], aBase + ko);
            ldsm4(a[1][0], a[1][1], a[1][2], a[1][3], aBase + ko + 16 * 80);
#pragma unroll
            for (int ntp = 0; ntp < 4; ntp++) {
                uint32_t b0, b1, b2, b3;
                ldsm4(b0, b1, b2, b3, bBase + ko + (uint32_t)(ntp * 16 * 80));
                mma_bf16(c[0][2 * ntp],     a[0], b0, b2);
                mma_bf16(c[0][2 * ntp + 1], a[0], b1, b3);
                mma_bf16(c[1][2 * ntp],     a[1], b0, b2);
                mma_bf16(c[1][2 * ntp + 1], a[1], b1, b3);
            }
        }
        __syncthreads();
    }
#undef LOAD_STAGE

    // scale + diagonal mask
#pragma unroll
    for (int mt = 0; mt < 2; mt++)
#pragma unroll
        for (int nt = 0; nt < 8; nt++)
#pragma unroll
            for (int q = 0; q < 4; q++) c[mt][nt][q] *= TEMP_INV;

    if (bi == bj) {
#pragma unroll
        for (int mt = 0; mt < 2; mt++) {
            int gi0 = wr * 32 + mt * 16 + grp;
#pragma unroll
            for (int nt = 0; nt < 8; nt++) {
                int gj = wc * 64 + nt * 8 + 2 * tig;
                if (gi0 == gj)         c[mt][nt][0] = -1e9f;
                if (gi0 == gj + 1)     c[mt][nt][1] = -1e9f;
                if (gi0 + 8 == gj)     c[mt][nt][2] = -1e9f;
                if (gi0 + 8 == gj + 1) c[mt][nt][3] = -1e9f;
            }
        }
    }

    // store tile as fp16 (half2 per register pair)
#pragma unroll
    for (int mt = 0; mt < 2; mt++) {
        int gi0 = rowA + wr * 32 + mt * 16 + grp;
#pragma unroll
        for (int nt = 0; nt < 8; nt++) {
            int gj = rowB + wc * 64 + nt * 8 + 2 * tig;
            *(__half2*)&g_sim[(size_t)gi0 * B + gj] =
                __floats2half2_rn(c[mt][nt][0], c[mt][nt][1]);
            *(__half2*)&g_sim[(size_t)(gi0 + 8) * B + gj] =
                __floats2half2_rn(c[mt][nt][2], c[mt][nt][3]);
        }
    }

    // masked-exp partial sums, both directions, one ex2 per element
    float colacc[16];
#pragma unroll
    for (int k = 0; k < 16; k++) colacc[k] = 0.0f;

#pragma unroll
    for (int mt = 0; mt < 2; mt++) {
#pragma unroll
        for (int rr = 0; rr < 2; rr++) {
            int rloc = wr * 32 + mt * 16 + rr * 8 + grp;
            int labr = lA[rloc];
            float ra = 0.0f;
#pragma unroll
            for (int nt = 0; nt < 8; nt++) {
#pragma unroll
                for (int q = 0; q < 2; q++) {
                    int cloc = wc * 64 + nt * 8 + 2 * tig + q;
                    float v = c[mt][nt][rr * 2 + q];
                    float e = ex2a((v - MFIX) * LOG2E);
                    e = (lB[cloc] != labr) ? e : 0.0f;
                    ra += e;
                    colacc[nt * 2 + q] += e;
                }
            }
            ra += __shfl_xor_sync(0xFFFFFFFFu, ra, 1);
            ra += __shfl_xor_sync(0xFFFFFFFFu, ra, 2);
            if (tig == 0) red_s[wc][rloc] = ra;
        }
    }
    __syncthreads();
    if (t < TILE) g_ps[bj * B + rowA + t] = red_s[0][t] + red_s[1][t];

    if (bi < bj) {
        __syncthreads();
#pragma unroll
        for (int k = 0; k < 16; k++) {
            colacc[k] += __shfl_xor_sync(0xFFFFFFFFu, colacc[k], 4);
            colacc[k] += __shfl_xor_sync(0xFFFFFFFFu, colacc[k], 8);
            colacc[k] += __shfl_xor_sync(0xFFFFFFFFu, colacc[k], 16);
        }
        if (grp == 0) {
#pragma unroll
            for (int nt = 0; nt < 8; nt++)
#pragma unroll
                for (int q = 0; q < 2; q++) {
                    int cloc = wc * 64 + nt * 8 + 2 * tig + q;
                    red_s[wr][cloc] = colacc[nt * 2 + q];
                }
        }
        __syncthreads();
        if (t < TILE)
            g_ps[bi * B + rowB + t] =
                red_s[0][t] + red_s[1][t] + red_s[2][t] + red_s[3][t];
    }
}

// -------- 3: pair sum (fp16 sim reads) + fused last-block finalize ---------
__global__ __launch_bounds__(256) void pair_kernel(const int* __restrict__ labels,
                                                   float* __restrict__ out) {
    int bi, bj;
    tri_decode(blockIdx.x, bi, bj);
    int rowA = bi * TILE, rowB = bj * TILE;

    __shared__ float lseA[TILE], lseB[TILE];
    __shared__ int   lA[TILE], lB[TILE];
    int t = threadIdx.x;

    // prologue: lse_i = 10 + log( sum_k g_ps[k][i] )
    {
        int half_ = t >> 7;
        int u = t & 127;
        int gi = (half_ ? rowB : rowA) + u;
        float S = 0.0f;
#pragma unroll
        for (int k = 0; k < NBLK; k++) S += g_ps[k * B + gi];
        float lse = MFIX + logf(S);
        if (half_) { lseB[u] = lse; lB[u] = labels[gi]; }
        else       { lseA[u] = lse; lA[u] = labels[gi]; }
    }
    __syncthreads();

    int r = t >> 1;
    int cbase = (t & 1) * 64;
    int la = lA[r];
    float lsa = lseA[r];
    int dcol = (bi == bj) ? r : -1;
    bool off = (bi < bj);

    const uint4* rowp = (const uint4*)&g_sim[(size_t)(rowA + r) * B + rowB + cbase];
    float acc = 0.0f, prod = 1.0f;

#pragma unroll
    for (int k = 0; k < 8; k++) {        // 8 halves per uint4, 64 cols total
        uint4 u = rowp[k];
        int c0 = cbase + 8 * k;
        uint32_t uu[4] = {u.x, u.y, u.z, u.w};
        int4   lb0 = *(const int4*)&lB[c0];
        int4   lb1 = *(const int4*)&lB[c0 + 4];
        float4 ls0 = *(const float4*)&lseB[c0];
        float4 ls1 = *(const float4*)&lseB[c0 + 4];
        int   lbv[8] = {lb0.x, lb0.y, lb0.z, lb0.w, lb1.x, lb1.y, lb1.z, lb1.w};
        float lsb[8] = {ls0.x, ls0.y, ls0.z, ls0.w, ls1.x, ls1.y, ls1.z, ls1.w};
        float sv[8];
#pragma unroll
        for (int h = 0; h < 4; h++) {
            float2 f = __half22float2(*(const __half2*)&uu[h]);
            sv[2 * h] = f.x; sv[2 * h + 1] = f.y;
        }
#pragma unroll
        for (int q = 0; q < 8; q++) {
            bool m = (la == lbv[q]) && (c0 + q != dcol);
            if (m) {
                float s = sv[q];
                float x1 = lsa - s;
                acc += fmaxf(x1, 0.0f);
                float e1 = ex2a(-LOG2E * fabsf(x1));
                prod = fmaf(prod, e1, prod);
                if (off) {
                    float x2 = lsb[q] - s;
                    acc += fmaxf(x2, 0.0f);
                    float e2 = ex2a(-LOG2E * fabsf(x2));
                    prod = fmaf(prod, e2, prod);
                }
            }
        }
        if (k & 1) { acc += lg2a(prod) * LN2; prod = 1.0f; }
    }

    __shared__ float sh[256];
    float tot = block_reduce_sum(acc, sh);
    if (t == 0) {
        atomicAdd(&g_acc[6], tot);
        __threadfence();
        unsigned done = atomicAdd(&g_done, 1u);
        if (done == NTRI - 1) {
            volatile float* a = g_acc;
            float focal = a[0] / (float)B;
            float pd_cnt = a[1], ct_cnt = a[2];
            float pd = (pd_cnt > 0.0f) ? a[3] / pd_cnt : 0.0f;
            float ct = (ct_cnt > 0.0f) ? a[4] / ct_cnt : 0.0f;
            float ce = a[5] / (float)B;
            float reg = (pd + ct + ce) / ((float)(NR * (NR - 1)) * 0.5f + (float)NR);
            float cont = a[6] / (float)B;
            out[0] = 1.0f * focal + 0.5f * cont + 0.3f * reg;
#pragma unroll
            for (int k = 0; k < 8; k++) g_acc[k] = 0.0f;
            g_done = 0u;
        }
    }
}

// -------- launch -----------------------------------------------------------
extern "C" void kernel_launch(void* const* d_in, const int* in_sizes, int n_in,
                              void* d_out, int out_size) {
    const float* logits = (const float*)d_in[0];
    const float* proj   = (const float*)d_in[1];
    const float* rp     = (const float*)d_in[2];
    const int*   labels = (const int*)d_in[3];
    float* out = (float*)d_out;
    (void)in_sizes; (void)n_in; (void)out_size;

    prep_kernel<<<B / 8, 256>>>(proj, logits, rp, labels);
    sim_kernel<<<NTRI, 256>>>(labels);
    pair_kernel<<<NTRI, 256>>>(labels, out);
}